// round 6
// baseline (speedup 1.0000x reference)
#include <cuda_runtime.h>

#define WIDTH    512
#define HEIGHT   512
#define TH       64
#define TH_IN    (TH + 10)            // 74 input rows per strip
#define STRIPS   (HEIGHT / TH)        // 8
#define QUARTERS 4
#define CHANNELS 96                   // 32 * 3
#define NBLK     (QUARTERS * STRIPS * CHANNELS) // 3072

#define C1v 1.0e-4f
#define C2v 9.0e-4f

typedef unsigned long long u64;

// Gaussian(sigma=1.5, k=11) weights; symmetric: KW[i] == KW[10-i].
#define DECL_KW \
    constexpr float KW[6] = { \
        0.00102838f, 0.00759876f, 0.03600078f, 0.10936081f, 0.21300554f, \
        0.26601173f }

// ---- packed f32x2 helpers (PTX-only on sm_103a) ----
__device__ __forceinline__ u64 pack2(float lo, float hi) {
    u64 r; asm("mov.b64 %0, {%1, %2};" : "=l"(r) : "f"(lo), "f"(hi)); return r;
}
__device__ __forceinline__ void unpack2(u64 v, float& lo, float& hi) {
    asm("mov.b64 {%0, %1}, %2;" : "=f"(lo), "=f"(hi) : "l"(v));
}
__device__ __forceinline__ u64 fma2(u64 a, u64 b, u64 c) {
    u64 d; asm("fma.rn.f32x2 %0, %1, %2, %3;" : "=l"(d) : "l"(a), "l"(b), "l"(c)); return d;
}
__device__ __forceinline__ u64 mul2(u64 a, u64 b) {
    u64 d; asm("mul.rn.f32x2 %0, %1, %2;" : "=l"(d) : "l"(a), "l"(b)); return d;
}
__device__ __forceinline__ u64 add2(u64 a, u64 b) {
    u64 d; asm("add.rn.f32x2 %0, %1, %2;" : "=l"(d) : "l"(a), "l"(b)); return d;
}

__device__ float g_partial[NBLK];
__device__ int   g_count = 0;

__global__ void __launch_bounds__(128, 6)
ssim_main(const float* __restrict__ pred, const float* __restrict__ targ,
          float* __restrict__ out) {
    DECL_KW;
    // Warp-private staging: 42 packed (e,d) per warp per buffer
    // (32 own cols + 5 halo each side), double-buffered; only __syncwarp().
    __shared__ u64    sW[2][4][44];
    __shared__ float  wsum[4];
    __shared__ double dsh[128];
    __shared__ int    sIsLast;

    const int tid = threadIdx.x;
    const int w   = tid >> 5;
    const int l   = tid & 31;
    const int quarter = blockIdx.x & 3;
    const int strip   = blockIdx.x >> 2;
    const int ch      = blockIdx.y;
    const int y0      = strip * TH;
    const int colbase = quarter * 128 + w * 32;
    const int c0 = colbase + l;

    // halo assignment for lanes 0..9
    int hidx = 0, chalo = 0; bool hval = false;
    if (l < 5)       { chalo = colbase - 5 + l;  hidx = l;      hval = (chalo >= 0); }
    else if (l < 10) { chalo = colbase + 27 + l; hidx = 32 + l; hval = (chalo < WIDTH); }

    const float* __restrict__ P = pred + (size_t)ch * (WIDTH * HEIGHT);
    const float* __restrict__ T = targ + (size_t)ch * (WIDTH * HEIGHT);

    // packed symmetric weights (6 distinct)
    u64 KW2[6];
    #pragma unroll
    for (int i = 0; i < 6; i++) KW2[i] = pack2(KW[i], KW[i]);

    // vertical ring over 11 horizontal-conv result rows (packed)
    u64 rH[11], rH2[11];
    float acc = 0.f;

    // prefetch input row k=0 (abs y0-5)
    float pN = 0.f, tN = 0.f, pHN = 0.f, tHN = 0.f;
    {
        const int r = y0 - 5;
        if ((unsigned)r < (unsigned)HEIGHT) {
            pN = P[r * WIDTH + c0];
            tN = T[r * WIDTH + c0];
            if (hval) { pHN = P[r * WIDTH + chalo]; tHN = T[r * WIDTH + chalo]; }
        }
    }

    #pragma unroll 1
    for (int kc = 0; kc < TH_IN; kc += 11) {
        #pragma unroll
        for (int u = 0; u < 11; u++) {
            const int k = kc + u;
            if (k >= TH_IN) break;   // uniform

            const float p = pN, t = tN, ph = pHN, th = tHN;
            if (k + 1 < TH_IN) {     // prefetch abs row y0-4+k
                const int r = y0 - 4 + k;
                if ((unsigned)r < (unsigned)HEIGHT) {
                    pN = P[r * WIDTH + c0];
                    tN = T[r * WIDTH + c0];
                    if (hval) { pHN = P[r * WIDTH + chalo]; tHN = T[r * WIDTH + chalo]; }
                    else      { pHN = 0.f; tHN = 0.f; }
                } else { pN = 0.f; tN = 0.f; pHN = 0.f; tHN = 0.f; }
            }

            const int buf = k & 1;
            sW[buf][w][5 + l] = pack2(p + t, p - t);
            if (l < 10) sW[buf][w][hidx] = pack2(ph + th, ph - th);
            __syncwarp();

            // horizontal conv: symmetric pairs + dual accumulators
            u64 hA = 0ull, hB = 0ull, h2A = 0ull, h2B = 0ull;
            #pragma unroll
            for (int i = 0; i < 5; i++) {
                const u64 va = sW[buf][w][l + i];
                const u64 vb = sW[buf][w][l + 10 - i];
                const u64 s  = add2(va, vb);
                const u64 q  = add2(mul2(va, va), mul2(vb, vb));
                if (i & 1) { hB = fma2(s, KW2[i], hB); h2B = fma2(q, KW2[i], h2B); }
                else       { hA = fma2(s, KW2[i], hA); h2A = fma2(q, KW2[i], h2A); }
            }
            {
                const u64 v5 = sW[buf][w][l + 5];
                hA  = fma2(v5,           KW2[5], hA);
                h2A = fma2(mul2(v5, v5), KW2[5], h2A);
            }
            rH[u]  = add2(hA, hB);
            rH2[u] = add2(h2A, h2B);

            // vertical conv + SSIM once ring full (output row k-10)
            if (k >= 10) {
                u64 mA = 0ull, mB = 0ull, cA = 0ull, cB = 0ull;
                #pragma unroll
                for (int i = 0; i < 5; i++) {
                    const int sa = (u + 1 + i) % 11;
                    const int sb = (u + 11 - i) % 11;   // (u+1+10-i)%11
                    const u64 sm = add2(rH[sa],  rH[sb]);
                    const u64 sc = add2(rH2[sa], rH2[sb]);
                    if (i & 1) { mB = fma2(sm, KW2[i], mB); cB = fma2(sc, KW2[i], cB); }
                    else       { mA = fma2(sm, KW2[i], mA); cA = fma2(sc, KW2[i], cA); }
                }
                {
                    const int s5 = (u + 6) % 11;
                    mA = fma2(rH[s5],  KW2[5], mA);
                    cA = fma2(rH2[s5], KW2[5], cA);
                }
                float me, md, ce2, cd2;
                unpack2(add2(mA, mB), me, md);
                unpack2(add2(cA, cB), ce2, cd2);
                const float A  = me * me;
                const float B  = md * md;
                const float t1 = A - B;
                const float t2 = A + B;
                const float n1 = fmaf(0.5f, t1, C1v);
                const float d1 = fmaf(0.5f, t2, C1v);
                const float n2 = fmaf(0.5f, (ce2 - cd2) - t1, C2v);
                const float d2 = fmaf(0.5f, (ce2 + cd2) - t2, C2v);
                acc += __fdividef(n1 * n2, d1 * d2);
            }
        }
    }

    // deterministic block reduction (one barrier, at the end)
    #pragma unroll
    for (int o = 16; o > 0; o >>= 1)
        acc += __shfl_down_sync(0xffffffffu, acc, o);
    if (l == 0) wsum[w] = acc;
    __syncthreads();
    if (tid < 32) {
        float v = (l < 4) ? wsum[l] : 0.f;
        v += __shfl_down_sync(0xffffffffu, v, 2);
        v += __shfl_down_sync(0xffffffffu, v, 1);
        if (l == 0)
            g_partial[blockIdx.y * (QUARTERS * STRIPS) + blockIdx.x] = v;
    }

    // deterministic last-block final reduction (fp64, fixed order)
    if (tid == 0) {
        __threadfence();
        const int n = atomicAdd(&g_count, 1);
        sIsLast = (n == NBLK - 1);
    }
    __syncthreads();
    if (sIsLast) {
        __threadfence();
        double s = 0.0;
        for (int i = tid; i < NBLK; i += 128)
            s += (double)g_partial[i];
        dsh[tid] = s;
        __syncthreads();
        #pragma unroll 1
        for (int o = 64; o > 0; o >>= 1) {
            if (tid < o) dsh[tid] += dsh[tid + o];
            __syncthreads();
        }
        if (tid == 0) {
            out[0] = (float)(1.0 - dsh[0] / 25165824.0);  // 32*3*512*512
            g_count = 0;  // reset for next graph replay
        }
    }
}

extern "C" void kernel_launch(void* const* d_in, const int* in_sizes, int n_in,
                              void* d_out, int out_size) {
    const float* pred = (const float*)d_in[0];
    const float* targ = (const float*)d_in[1];
    ssim_main<<<dim3(QUARTERS * STRIPS, CHANNELS), 128>>>(pred, targ, (float*)d_out);
}